// round 5
// baseline (speedup 1.0000x reference)
#include <cuda_runtime.h>
#include <cstdint>

#define BATCH 8192
#define K_IN  1024
#define NDIM  2048
#define TWO_N 4096

// 128 MB scratch for inputs_mul = inputs @ w_ih^T  (allocation-free rule: device global)
__device__ float g_mul[(size_t)BATCH * TWO_N];

// ============================================================================
// GEMM: C[8192,4096] = A[8192,1024] * W[4096,1024]^T   (tf32 mma.sync, fp32 accum)
// ============================================================================
#define BM 128
#define BN 128
#define BK 16
#define NIT (K_IN / BK)   // 64

__device__ __forceinline__ uint32_t f2tf32(float x) {
    uint32_t r;
    asm("cvt.rna.tf32.f32 %0, %1;" : "=r"(r) : "f"(x));
    return r;
}

__device__ __forceinline__ void cp16(void* dst_smem, const void* src) {
    uint32_t d = (uint32_t)__cvta_generic_to_shared(dst_smem);
    asm volatile("cp.async.cg.shared.global [%0], [%1], 16;" :: "r"(d), "l"(src) : "memory");
}

__device__ __forceinline__ void mma_tf32(float* c, const uint32_t* a, const uint32_t* b) {
    asm volatile(
        "mma.sync.aligned.m16n8k8.row.col.f32.tf32.tf32.f32 "
        "{%0,%1,%2,%3}, {%4,%5,%6,%7}, {%8,%9}, {%0,%1,%2,%3};\n"
        : "+f"(c[0]), "+f"(c[1]), "+f"(c[2]), "+f"(c[3])
        : "r"(a[0]), "r"(a[1]), "r"(a[2]), "r"(a[3]), "r"(b[0]), "r"(b[1]));
}

__global__ __launch_bounds__(256) void gemm_tf32_kernel(
    const float* __restrict__ A, const float* __restrict__ W)
{
    // [m][k] layout, +4 pad -> stride 20 floats: fragment LDS is conflict-free
    __shared__ float As[2][BM][BK + 4];
    __shared__ float Bs[2][BN][BK + 4];

    const int tid  = threadIdx.x;
    const int warp = tid >> 5, lane = tid & 31;
    const int g = lane >> 2, t = lane & 3;
    const int wm = (warp & 1) * 64;   // warp tile 64(M) x 32(N), 2x4 warp grid
    const int wn = (warp >> 1) * 32;
    const int bm = blockIdx.y * BM;
    const int bn = blockIdx.x * BN;

    const int lr = tid >> 2;          // 0..63 -> rows lr, lr+64
    const int lc = (tid & 3) * 4;     // k offset 0,4,8,12

    float acc[4][4][4];
    #pragma unroll
    for (int mi = 0; mi < 4; ++mi)
        #pragma unroll
        for (int ni = 0; ni < 4; ++ni)
            #pragma unroll
            for (int r = 0; r < 4; ++r) acc[mi][ni][r] = 0.0f;

    // prologue: stage 0
    {
        const float* a0 = A + (size_t)(bm + lr) * K_IN + lc;
        const float* b0 = W + (size_t)(bn + lr) * K_IN + lc;
        cp16(&As[0][lr][lc],      a0);
        cp16(&As[0][lr + 64][lc], a0 + (size_t)64 * K_IN);
        cp16(&Bs[0][lr][lc],      b0);
        cp16(&Bs[0][lr + 64][lc], b0 + (size_t)64 * K_IN);
        asm volatile("cp.async.commit_group;");
    }

    for (int it = 0; it < NIT; ++it) {
        if (it + 1 < NIT) {
            const int k0 = (it + 1) * BK;
            const int ns = (it + 1) & 1;
            const float* a0 = A + (size_t)(bm + lr) * K_IN + k0 + lc;
            const float* b0 = W + (size_t)(bn + lr) * K_IN + k0 + lc;
            cp16(&As[ns][lr][lc],      a0);
            cp16(&As[ns][lr + 64][lc], a0 + (size_t)64 * K_IN);
            cp16(&Bs[ns][lr][lc],      b0);
            cp16(&Bs[ns][lr + 64][lc], b0 + (size_t)64 * K_IN);
            asm volatile("cp.async.commit_group;");
            asm volatile("cp.async.wait_group 1;");
        } else {
            asm volatile("cp.async.wait_group 0;");
        }
        __syncthreads();

        const int s = it & 1;
        #pragma unroll
        for (int kk = 0; kk < BK; kk += 8) {
            uint32_t af[4][4], bf[4][2];
            #pragma unroll
            for (int mi = 0; mi < 4; ++mi) {
                const int m = wm + mi * 16 + g;
                af[mi][0] = f2tf32(As[s][m][kk + t]);
                af[mi][1] = f2tf32(As[s][m + 8][kk + t]);
                af[mi][2] = f2tf32(As[s][m][kk + t + 4]);
                af[mi][3] = f2tf32(As[s][m + 8][kk + t + 4]);
            }
            #pragma unroll
            for (int ni = 0; ni < 4; ++ni) {
                const int n = wn + ni * 8 + g;
                bf[ni][0] = f2tf32(Bs[s][n][kk + t]);
                bf[ni][1] = f2tf32(Bs[s][n][kk + t + 4]);
            }
            #pragma unroll
            for (int mi = 0; mi < 4; ++mi)
                #pragma unroll
                for (int ni = 0; ni < 4; ++ni)
                    mma_tf32(acc[mi][ni], af[mi], bf[ni]);
        }
        __syncthreads();
    }

    // epilogue: c0,c1 at (g, 2t/2t+1), c2,c3 at (g+8, same cols)
    #pragma unroll
    for (int mi = 0; mi < 4; ++mi)
        #pragma unroll
        for (int ni = 0; ni < 4; ++ni) {
            const int m = bm + wm + mi * 16 + g;
            const int n = bn + wn + ni * 8 + 2 * t;
            float2 v0 = make_float2(acc[mi][ni][0], acc[mi][ni][1]);
            float2 v1 = make_float2(acc[mi][ni][2], acc[mi][ni][3]);
            *(float2*)&g_mul[(size_t)m * TWO_N + n]       = v0;
            *(float2*)&g_mul[(size_t)(m + 8) * TWO_N + n] = v1;
        }
}

// ============================================================================
// Fused per-row URNN: d1 -> FFT -> reflect1 -> perm -> d2 -> iFFT -> reflect2
//                     -> d3 (+1/N) -> + inputs_c -> modReLU -> store
// One CTA per batch row. Whole 2048-pt complex row in SMEM (SoA).
// ============================================================================
#define RT  256
#define EPT 8   // 2048 / 256

// XOR swizzle: kills 32-way stride-64 bank conflicts of the bit-reversal pass;
// keeps consecutive-index accesses conflict-free (flips only bits [0:5)).
#define SW(i) ((i) ^ (((i) >> 6) & 31))

__device__ __forceinline__ void fft2048(float* sre, float* sim, int tid, float sgn)
{
    // bit-reversal reorder (read natural, write reversed; rev is an involution)
    float tre[EPT], tim[EPT];
    #pragma unroll
    for (int j = 0; j < EPT; ++j) {
        const int i = tid + j * RT;
        tre[j] = sre[SW(i)];
        tim[j] = sim[SW(i)];
    }
    __syncthreads();
    #pragma unroll
    for (int j = 0; j < EPT; ++j) {
        const int i = tid + j * RT;
        const int r = (int)(__brev((unsigned)i) >> 21);   // 11-bit reverse
        sre[SW(r)] = tre[j];
        sim[SW(r)] = tim[j];
    }
    __syncthreads();

    // 11 radix-2 DIT stages; twiddle = exp(sgn * i * pi * pos / mh)
    #pragma unroll 1
    for (int s = 1; s <= 11; ++s) {
        const int mh = 1 << (s - 1);
        const float astep = sgn * 3.14159265358979f / (float)mh;
        #pragma unroll
        for (int j = 0; j < EPT / 2; ++j) {               // 1024 butterflies / 256
            const int idx  = tid + j * RT;
            const int pos  = idx & (mh - 1);
            const int base = ((idx >> (s - 1)) << s) + pos;
            float c, sn;
            __sincosf(astep * (float)pos, &sn, &c);
            const int i0 = SW(base), i1 = SW(base + mh);
            const float ar = sre[i0], ai = sim[i0];
            const float br = sre[i1], bi = sim[i1];
            const float trr = c * br - sn * bi;
            const float tri = c * bi + sn * br;
            sre[i0] = ar + trr; sim[i0] = ai + tri;
            sre[i1] = ar - trr; sim[i1] = ai - tri;
        }
        __syncthreads();
    }
}

__device__ __forceinline__ void reflect2048(float* sre, float* sim,
    const float* __restrict__ vre, const float* __restrict__ vim,
    float* red, int tid)
{
    float sq = 0.f, dr = 0.f, di = 0.f;
    #pragma unroll
    for (int j = 0; j < EPT; ++j) {
        const int i = tid + j * RT;
        const float vr = vre[i], vi = vim[i];
        const float zr = sre[SW(i)], zi = sim[SW(i)];
        sq += vr * vr + vi * vi;
        dr += zr * vr + zi * vi;     // Re(z * conj(v))
        di += zi * vr - zr * vi;     // Im(z * conj(v))
    }
    #pragma unroll
    for (int off = 16; off > 0; off >>= 1) {
        sq += __shfl_down_sync(0xffffffffu, sq, off);
        dr += __shfl_down_sync(0xffffffffu, dr, off);
        di += __shfl_down_sync(0xffffffffu, di, off);
    }
    const int warp = tid >> 5, lane = tid & 31;
    if (lane == 0) { red[warp] = sq; red[8 + warp] = dr; red[16 + warp] = di; }
    __syncthreads();
    if (tid == 0) {
        float a = 0.f, b = 0.f, c = 0.f;
        #pragma unroll
        for (int w = 0; w < 8; ++w) { a += red[w]; b += red[8 + w]; c += red[16 + w]; }
        const float f = 2.0f / a;
        red[24] = f * b;
        red[25] = f * c;
    }
    __syncthreads();
    const float cr = red[24], ci = red[25];
    #pragma unroll
    for (int j = 0; j < EPT; ++j) {
        const int i  = tid + j * RT;
        const float vr = vre[i], vi = vim[i];
        const int ii = SW(i);
        sre[ii] -= cr * vr - ci * vi;
        sim[ii] -= cr * vi + ci * vr;
    }
    __syncthreads();
}

__global__ __launch_bounds__(RT) void urnn_row_kernel(
    const float* __restrict__ state,
    const float* __restrict__ b_h,
    const float* __restrict__ d1, const float* __restrict__ r1re, const float* __restrict__ r1im,
    const float* __restrict__ d2, const float* __restrict__ r2re, const float* __restrict__ r2im,
    const float* __restrict__ d3, const int* __restrict__ perm,
    float* __restrict__ out)
{
    __shared__ float sre[NDIM], sim[NDIM];
    __shared__ float red[32];

    const int tid = threadIdx.x;
    const size_t row = (size_t)blockIdx.x * TWO_N;
    const float* st   = state + row;
    const float* mrow = g_mul + row;
    float*       orow = out + row;

    // load state_c and apply d1 rotation
    #pragma unroll
    for (int j = 0; j < EPT; ++j) {
        const int i = tid + j * RT;
        const float re = st[i], im = st[i + NDIM];
        float c, s;
        __sincosf(d1[i], &s, &c);
        sre[SW(i)] = c * re - s * im;
        sim[SW(i)] = c * im + s * re;
    }
    __syncthreads();

    fft2048(sre, sim, tid, -1.0f);                 // forward FFT
    reflect2048(sre, sim, r1re, r1im, red, tid);   // reflect 1

    // permutation gather (new[i] = old[perm[i]]) fused with d2 rotation
    {
        float tre[EPT], tim[EPT];
        #pragma unroll
        for (int j = 0; j < EPT; ++j) {
            const int i = tid + j * RT;
            const int p = perm[i];
            tre[j] = sre[SW(p)];
            tim[j] = sim[SW(p)];
        }
        __syncthreads();
        #pragma unroll
        for (int j = 0; j < EPT; ++j) {
            const int i = tid + j * RT;
            float c, s;
            __sincosf(d2[i], &s, &c);
            sre[SW(i)] = c * tre[j] - s * tim[j];
            sim[SW(i)] = c * tim[j] + s * tre[j];
        }
        __syncthreads();
    }

    fft2048(sre, sim, tid, +1.0f);                 // inverse FFT (unnormalized; 1/N folded below)
    reflect2048(sre, sim, r2re, r2im, red, tid);   // reflect 2 (linear -> scale commutes)

    // d3 rotation * 1/N, add inputs_c, modReLU, store [re | im]
    const float invn = 1.0f / (float)NDIM;
    #pragma unroll
    for (int j = 0; j < EPT; ++j) {
        const int i = tid + j * RT;
        const float zr0 = sre[SW(i)], zi0 = sim[SW(i)];
        float c, s;
        __sincosf(d3[i], &s, &c);
        const float zr = (c * zr0 - s * zi0) * invn;
        const float zi = (c * zi0 + s * zr0) * invn;
        const float pr = mrow[i] + zr;
        const float pi = mrow[i + NDIM] + zi;
        const float nrm = sqrtf(pr * pr + pi * pi);
        const float sc = fmaxf(nrm + b_h[i], 0.0f) / (nrm + 1e-6f);
        orow[i]        = pr * sc;
        orow[i + NDIM] = pi * sc;
    }
}

// ============================================================================
extern "C" void kernel_launch(void* const* d_in, const int* in_sizes, int n_in,
                              void* d_out, int out_size)
{
    const float* inputs = (const float*)d_in[0];
    const float* state  = (const float*)d_in[1];
    const float* w_ih   = (const float*)d_in[2];
    const float* b_h    = (const float*)d_in[3];
    const float* d1     = (const float*)d_in[4];
    const float* r1re   = (const float*)d_in[5];
    const float* r1im   = (const float*)d_in[6];
    const float* d2     = (const float*)d_in[7];
    const float* r2re   = (const float*)d_in[8];
    const float* r2im   = (const float*)d_in[9];
    const float* d3     = (const float*)d_in[10];
    const int*   perm   = (const int*)d_in[11];
    float* out = (float*)d_out;

    dim3 ggrid(TWO_N / BN, BATCH / BM);       // (32, 64)
    gemm_tf32_kernel<<<ggrid, 256>>>(inputs, w_ih);
    urnn_row_kernel<<<BATCH, RT>>>(state, b_h, d1, r1re, r1im,
                                   d2, r2re, r2im, d3, perm, out);
}

// round 7
// speedup vs baseline: 1.0606x; 1.0606x over previous
#include <cuda_runtime.h>
#include <cstdint>

#define BATCH 8192
#define K_IN  1024
#define NDIM  2048
#define TWO_N 4096

// 128 MB scratch for inputs_mul = inputs @ w_ih^T  (allocation-free rule: device global)
__device__ float g_mul[(size_t)BATCH * TWO_N];

// ============================================================================
// GEMM: C[8192,4096] = A[8192,1024] * W[4096,1024]^T   (tf32 mma.sync, fp32 accum)
// ============================================================================
#define BM 128
#define BN 128
#define BK 16
#define NIT (K_IN / BK)   // 64

__device__ __forceinline__ uint32_t f2tf32(float x) {
    uint32_t r;
    asm("cvt.rna.tf32.f32 %0, %1;" : "=r"(r) : "f"(x));
    return r;
}

__device__ __forceinline__ void cp16(void* dst_smem, const void* src) {
    uint32_t d = (uint32_t)__cvta_generic_to_shared(dst_smem);
    asm volatile("cp.async.cg.shared.global [%0], [%1], 16;" :: "r"(d), "l"(src) : "memory");
}

__device__ __forceinline__ void mma_tf32(float* c, const uint32_t* a, const uint32_t* b) {
    asm volatile(
        "mma.sync.aligned.m16n8k8.row.col.f32.tf32.tf32.f32 "
        "{%0,%1,%2,%3}, {%4,%5,%6,%7}, {%8,%9}, {%0,%1,%2,%3};\n"
        : "+f"(c[0]), "+f"(c[1]), "+f"(c[2]), "+f"(c[3])
        : "r"(a[0]), "r"(a[1]), "r"(a[2]), "r"(a[3]), "r"(b[0]), "r"(b[1]));
}

__global__ __launch_bounds__(256) void gemm_tf32_kernel(
    const float* __restrict__ A, const float* __restrict__ W)
{
    __shared__ float As[2][BM][BK + 4];
    __shared__ float Bs[2][BN][BK + 4];

    const int tid  = threadIdx.x;
    const int warp = tid >> 5, lane = tid & 31;
    const int g = lane >> 2, t = lane & 3;
    const int wm = (warp & 1) * 64;   // warp tile 64(M) x 32(N), 2x4 warp grid
    const int wn = (warp >> 1) * 32;
    const int bm = blockIdx.y * BM;
    const int bn = blockIdx.x * BN;

    const int lr = tid >> 2;          // 0..63 -> rows lr, lr+64
    const int lc = (tid & 3) * 4;     // k offset 0,4,8,12

    float acc[4][4][4];
    #pragma unroll
    for (int mi = 0; mi < 4; ++mi)
        #pragma unroll
        for (int ni = 0; ni < 4; ++ni)
            #pragma unroll
            for (int r = 0; r < 4; ++r) acc[mi][ni][r] = 0.0f;

    // prologue: stage 0
    {
        const float* a0 = A + (size_t)(bm + lr) * K_IN + lc;
        const float* b0 = W + (size_t)(bn + lr) * K_IN + lc;
        cp16(&As[0][lr][lc],      a0);
        cp16(&As[0][lr + 64][lc], a0 + (size_t)64 * K_IN);
        cp16(&Bs[0][lr][lc],      b0);
        cp16(&Bs[0][lr + 64][lc], b0 + (size_t)64 * K_IN);
        asm volatile("cp.async.commit_group;");
    }

    for (int it = 0; it < NIT; ++it) {
        asm volatile("cp.async.wait_group 0;");
        __syncthreads();                       // single barrier per iteration

        if (it + 1 < NIT) {
            const int k0 = (it + 1) * BK;
            const int ns = (it + 1) & 1;
            const float* a0 = A + (size_t)(bm + lr) * K_IN + k0 + lc;
            const float* b0 = W + (size_t)(bn + lr) * K_IN + k0 + lc;
            cp16(&As[ns][lr][lc],      a0);
            cp16(&As[ns][lr + 64][lc], a0 + (size_t)64 * K_IN);
            cp16(&Bs[ns][lr][lc],      b0);
            cp16(&Bs[ns][lr + 64][lc], b0 + (size_t)64 * K_IN);
            asm volatile("cp.async.commit_group;");
        }

        const int s = it & 1;
        #pragma unroll
        for (int kk = 0; kk < BK; kk += 8) {
            uint32_t af[4][4], bf[4][2];
            #pragma unroll
            for (int mi = 0; mi < 4; ++mi) {
                const int m = wm + mi * 16 + g;
                af[mi][0] = f2tf32(As[s][m][kk + t]);
                af[mi][1] = f2tf32(As[s][m + 8][kk + t]);
                af[mi][2] = f2tf32(As[s][m][kk + t + 4]);
                af[mi][3] = f2tf32(As[s][m + 8][kk + t + 4]);
            }
            #pragma unroll
            for (int ni = 0; ni < 4; ++ni) {
                const int n = wn + ni * 8 + g;
                bf[ni][0] = f2tf32(Bs[s][n][kk + t]);
                bf[ni][1] = f2tf32(Bs[s][n][kk + t + 4]);
            }
            #pragma unroll
            for (int mi = 0; mi < 4; ++mi)
                #pragma unroll
                for (int ni = 0; ni < 4; ++ni)
                    mma_tf32(acc[mi][ni], af[mi], bf[ni]);
        }
    }

    #pragma unroll
    for (int mi = 0; mi < 4; ++mi)
        #pragma unroll
        for (int ni = 0; ni < 4; ++ni) {
            const int m = bm + wm + mi * 16 + g;
            const int n = bn + wn + ni * 8 + 2 * t;
            float2 v0 = make_float2(acc[mi][ni][0], acc[mi][ni][1]);
            float2 v1 = make_float2(acc[mi][ni][2], acc[mi][ni][3]);
            *(float2*)&g_mul[(size_t)m * TWO_N + n]       = v0;
            *(float2*)&g_mul[(size_t)(m + 8) * TWO_N + n] = v1;
        }
}

// ============================================================================
// Fused per-row URNN, mixed-radix 8*8*8*4 register FFT.
// One CTA (256 threads) per batch row; row in SMEM (SoA re/im).
// XOR swizzle i ^ ((i>>3)&31): conflict-free for bit-reversed reads, all pass
// layouts, and linear accesses (verified per-pattern).
// ============================================================================
#define RT  256
#define SW(i) ((i) ^ (((i) >> 3) & 31))
#define FPI 3.14159265358979f

__device__ __forceinline__ void bfly(float& ar, float& ai, float& br, float& bi,
                                     float wr, float wi)
{
    const float tr = wr * br - wi * bi;
    const float ti = wr * bi + wi * br;
    br = ar - tr; bi = ai - ti;
    ar = ar + tr; ai = ai + ti;
}

// 3 radix-2 DIT stages (distances S, 2S, 4S) on 8 register-resident elements
// idx_e = base + e*S, low = base mod S, phi = sgn*pi*low/S.
__device__ __forceinline__ void radix8(float* xr, float* xi, float phi, float sgn)
{
    float c1, s1, c2, s2, c3, s3;
    __sincosf(phi,          &s1, &c1);
    __sincosf(phi * 0.50f,  &s2, &c2);
    __sincosf(phi * 0.25f,  &s3, &c3);
    // stage S: pairs (0,1)(2,3)(4,5)(6,7), w = cis(phi)
    bfly(xr[0], xi[0], xr[1], xi[1], c1, s1);
    bfly(xr[2], xi[2], xr[3], xi[3], c1, s1);
    bfly(xr[4], xi[4], xr[5], xi[5], c1, s1);
    bfly(xr[6], xi[6], xr[7], xi[7], c1, s1);
    // stage 2S: pairs (0,2)(4,6) w=cis(phi/2); (1,3)(5,7) w=cis(phi/2+sgn*pi/2)
    const float wbr = -sgn * s2, wbi = sgn * c2;
    bfly(xr[0], xi[0], xr[2], xi[2], c2, s2);
    bfly(xr[1], xi[1], xr[3], xi[3], wbr, wbi);
    bfly(xr[4], xi[4], xr[6], xi[6], c2, s2);
    bfly(xr[5], xi[5], xr[7], xi[7], wbr, wbi);
    // stage 4S: pairs (e, e+4), w = cis(phi/4) * cis(sgn*pi/4)^e
    const float h = 0.70710678118f;
    const float w1r = h * (c3 - sgn * s3), w1i = h * (sgn * c3 + s3);
    const float w2r = -sgn * s3,           w2i = sgn * c3;
    const float w3r = -h * (c3 + sgn * s3), w3i = h * (sgn * c3 - s3);
    bfly(xr[0], xi[0], xr[4], xi[4], c3, s3);
    bfly(xr[1], xi[1], xr[5], xi[5], w1r, w1i);
    bfly(xr[2], xi[2], xr[6], xi[6], w2r, w2i);
    bfly(xr[3], xi[3], xr[7], xi[7], w3r, w3i);
}

// 2 radix-2 DIT stages (distances S, 2S) on 4 elements; alpha = sgn*pi*low/S.
__device__ __forceinline__ void radix4(float* xr, float* xi, float alpha, float sgn)
{
    float c1, s1, c2, s2;
    __sincosf(alpha,         &s1, &c1);
    __sincosf(alpha * 0.5f,  &s2, &c2);
    bfly(xr[0], xi[0], xr[1], xi[1], c1, s1);
    bfly(xr[2], xi[2], xr[3], xi[3], c1, s1);
    const float wbr = -sgn * s2, wbi = sgn * c2;
    bfly(xr[0], xi[0], xr[2], xi[2], c2, s2);
    bfly(xr[1], xi[1], xr[3], xi[3], wbr, wbi);
}

// Full 2048-pt DIT FFT. Input: natural-order data in sre/sim (swizzled).
// Output: zr/zi[r*4+e] = X[tid + 256r + 512e] (natural order), kept in regs.
// Caller must __syncthreads() before calling (data visible) and after any
// subsequent smem write.
__device__ __forceinline__ void fft2048_r8(float* __restrict__ sre, float* __restrict__ sim,
                                           int tid, float sgn, float* zr, float* zi)
{
    float xr[8], xi[8];
    // ---- pass 1 (stages 1-3, S=1): bit-reversed gather ----
    const int rT = (int)(__brev((unsigned)tid) >> 24);   // rev8(tid)
    #pragma unroll
    for (int e = 0; e < 8; ++e) {
        const int r3 = ((e & 1) << 2) | (e & 2) | ((e & 4) >> 2);   // rev3(e)
        const int a = SW((r3 << 8) | rT);
        xr[e] = sre[a]; xi[e] = sim[a];
    }
    __syncthreads();                      // all reads done before scatter
    radix8(xr, xi, 0.0f, sgn);
    #pragma unroll
    for (int e = 0; e < 8; ++e) {
        const int a = SW(8 * tid + e);
        sre[a] = xr[e]; sim[a] = xi[e];
    }
    __syncthreads();
    // ---- pass 2 (stages 4-6, S=8) ----
    {
        const int low = tid & 7, base = ((tid >> 3) << 6) + low;
        #pragma unroll
        for (int e = 0; e < 8; ++e) { const int a = SW(base + 8 * e); xr[e] = sre[a]; xi[e] = sim[a]; }
        radix8(xr, xi, sgn * FPI * (float)low * 0.125f, sgn);
        #pragma unroll
        for (int e = 0; e < 8; ++e) { const int a = SW(base + 8 * e); sre[a] = xr[e]; sim[a] = xi[e]; }
    }
    __syncthreads();
    // ---- pass 3 (stages 7-9, S=64) ----
    {
        const int low = tid & 63, base = ((tid >> 6) << 9) + low;
        #pragma unroll
        for (int e = 0; e < 8; ++e) { const int a = SW(base + 64 * e); xr[e] = sre[a]; xi[e] = sim[a]; }
        radix8(xr, xi, sgn * FPI * (float)low * (1.0f / 64.0f), sgn);
        #pragma unroll
        for (int e = 0; e < 8; ++e) { const int a = SW(base + 64 * e); sre[a] = xr[e]; sim[a] = xi[e]; }
    }
    __syncthreads();
    // ---- pass 4 (stages 10-11, S=512): two radix-4 groups, results stay in regs ----
    #pragma unroll
    for (int r = 0; r < 2; ++r) {
        const int low = tid + 256 * r;
        float br[4], bi[4];
        #pragma unroll
        for (int e = 0; e < 4; ++e) { const int a = SW(low + 512 * e); br[e] = sre[a]; bi[e] = sim[a]; }
        radix4(br, bi, sgn * FPI * (float)low * (1.0f / 512.0f), sgn);
        #pragma unroll
        for (int e = 0; e < 4; ++e) { zr[r * 4 + e] = br[e]; zi[r * 4 + e] = bi[e]; }
    }
}

// Householder-style reflection applied to register-resident z
// (z index mapping: [r*4+e] <-> i = tid + 256r + 512e).
__device__ __forceinline__ void reflect_regs(float* zr, float* zi,
    const float* __restrict__ vre, const float* __restrict__ vim,
    float* red, int tid)
{
    float sq = 0.f, dr = 0.f, di = 0.f;
    #pragma unroll
    for (int r = 0; r < 2; ++r)
        #pragma unroll
        for (int e = 0; e < 4; ++e) {
            const int i = tid + 256 * r + 512 * e;
            const float vr = vre[i], vi = vim[i];
            const float a = zr[r * 4 + e], b = zi[r * 4 + e];
            sq += vr * vr + vi * vi;
            dr += a * vr + b * vi;     // Re(z * conj(v))
            di += b * vr - a * vi;     // Im(z * conj(v))
        }
    #pragma unroll
    for (int off = 16; off > 0; off >>= 1) {
        sq += __shfl_down_sync(0xffffffffu, sq, off);
        dr += __shfl_down_sync(0xffffffffu, dr, off);
        di += __shfl_down_sync(0xffffffffu, di, off);
    }
    const int warp = tid >> 5, lane = tid & 31;
    if (lane == 0) { red[warp] = sq; red[8 + warp] = dr; red[16 + warp] = di; }
    __syncthreads();
    if (tid == 0) {
        float a = 0.f, b = 0.f, c = 0.f;
        #pragma unroll
        for (int w = 0; w < 8; ++w) { a += red[w]; b += red[8 + w]; c += red[16 + w]; }
        const float f = 2.0f / a;
        red[24] = f * b;
        red[25] = f * c;
    }
    __syncthreads();
    const float cr = red[24], ci = red[25];
    #pragma unroll
    for (int r = 0; r < 2; ++r)
        #pragma unroll
        for (int e = 0; e < 4; ++e) {
            const int i = tid + 256 * r + 512 * e;
            const float vr = vre[i], vi = vim[i];
            zr[r * 4 + e] -= cr * vr - ci * vi;
            zi[r * 4 + e] -= cr * vi + ci * vr;
        }
}

__global__ __launch_bounds__(RT, 2) void urnn_row_kernel(
    const float* __restrict__ state,
    const float* __restrict__ b_h,
    const float* __restrict__ d1, const float* __restrict__ r1re, const float* __restrict__ r1im,
    const float* __restrict__ d2, const float* __restrict__ r2re, const float* __restrict__ r2im,
    const float* __restrict__ d3, const int* __restrict__ perm,
    float* __restrict__ out)
{
    __shared__ float sre[NDIM], sim[NDIM];
    __shared__ float red[32];

    const int tid = threadIdx.x;
    const size_t row = (size_t)blockIdx.x * TWO_N;
    const float* st   = state + row;
    const float* mrow = g_mul + row;
    float*       orow = out + row;

    float zr[8], zi[8];

    // ---- load state_c, apply d1 rotation, write natural order ----
    #pragma unroll
    for (int j = 0; j < 8; ++j) {
        const int i = tid + j * RT;
        const float re = st[i], im = st[i + NDIM];
        float c, s;
        __sincosf(d1[i], &s, &c);
        const int a = SW(i);
        sre[a] = c * re - s * im;
        sim[a] = c * im + s * re;
    }
    __syncthreads();

    // ---- forward FFT + reflection 1 (ends in regs) ----
    fft2048_r8(sre, sim, tid, -1.0f, zr, zi);
    reflect_regs(zr, zi, r1re, r1im, red, tid);

    // write corrected z back (each thread writes exactly the slots it read in pass 4)
    #pragma unroll
    for (int r = 0; r < 2; ++r)
        #pragma unroll
        for (int e = 0; e < 4; ++e) {
            const int i = tid + 256 * r + 512 * e;
            const int a = SW(i);
            sre[a] = zr[r * 4 + e]; sim[a] = zi[r * 4 + e];
        }
    __syncthreads();

    // ---- permutation gather fused with d2 rotation ----
    {
        float tre[8], tim[8];
        #pragma unroll
        for (int j = 0; j < 8; ++j) {
            const int i = tid + j * RT;
            const int p = perm[i];
            const int a = SW(p);
            tre[j] = sre[a]; tim[j] = sim[a];
        }
        __syncthreads();
        #pragma unroll
        for (int j = 0; j < 8; ++j) {
            const int i = tid + j * RT;
            float c, s;
            __sincosf(d2[i], &s, &c);
            const int a = SW(i);
            sre[a] = c * tre[j] - s * tim[j];
            sim[a] = c * tim[j] + s * tre[j];
        }
        __syncthreads();
    }

    // ---- inverse FFT (unnormalized; 1/N folded into epilogue) + reflection 2 ----
    fft2048_r8(sre, sim, tid, +1.0f, zr, zi);
    reflect_regs(zr, zi, r2re, r2im, red, tid);

    // ---- d3 rotation * 1/N, add inputs_c, modReLU, store (all coalesced) ----
    const float invn = 1.0f / (float)NDIM;
    #pragma unroll
    for (int r = 0; r < 2; ++r)
        #pragma unroll
        for (int e = 0; e < 4; ++e) {
            const int i = tid + 256 * r + 512 * e;
            const float zr0 = zr[r * 4 + e], zi0 = zi[r * 4 + e];
            float c, s;
            __sincosf(d3[i], &s, &c);
            const float zzr = (c * zr0 - s * zi0) * invn;
            const float zzi = (c * zi0 + s * zr0) * invn;
            const float pr = mrow[i] + zzr;
            const float pi = mrow[i + NDIM] + zzi;
            const float nrm = sqrtf(pr * pr + pi * pi);
            const float sc = fmaxf(nrm + b_h[i], 0.0f) / (nrm + 1e-6f);
            orow[i]        = pr * sc;
            orow[i + NDIM] = pi * sc;
        }
}

// ============================================================================
extern "C" void kernel_launch(void* const* d_in, const int* in_sizes, int n_in,
                              void* d_out, int out_size)
{
    const float* inputs = (const float*)d_in[0];
    const float* state  = (const float*)d_in[1];
    const float* w_ih   = (const float*)d_in[2];
    const float* b_h    = (const float*)d_in[3];
    const float* d1     = (const float*)d_in[4];
    const float* r1re   = (const float*)d_in[5];
    const float* r1im   = (const float*)d_in[6];
    const float* d2     = (const float*)d_in[7];
    const float* r2re   = (const float*)d_in[8];
    const float* r2im   = (const float*)d_in[9];
    const float* d3     = (const float*)d_in[10];
    const int*   perm   = (const int*)d_in[11];
    float* out = (float*)d_out;

    dim3 ggrid(TWO_N / BN, BATCH / BM);       // (32, 64)
    gemm_tf32_kernel<<<ggrid, 256>>>(inputs, w_ih);
    urnn_row_kernel<<<BATCH, RT>>>(state, b_h, d1, r1re, r1im,
                                   d2, r2re, r2im, d3, perm, out);
}